// round 6
// baseline (speedup 1.0000x reference)
#include <cuda_runtime.h>

// ---------------------------------------------------------------------------
// Problem constants
// ---------------------------------------------------------------------------
constexpr int Bb  = 2048;
constexpr int Nn  = 8;
constexpr int Tt  = 20;
constexpr int Mm  = Bb * Nn;        // 16384 sequences
constexpr int ES  = 64;
constexpr int HS  = 128;
constexpr int G3  = 3 * HS;         // 384
constexpr int RT  = Mm * Tt;        // 327680 rows (m*T + t)
constexpr int WTP = 388;            // weight tile pitch (16B-aligned rows, conflict-free)
constexpr int XP  = 128;            // gi x-tile pitch (dup over 64-k chunk)
constexpr int HP  = 260;            // scan h-tile pitch (dup over 128 k)
constexpr int OUT0 = Mm * 64;       // first output section ("out")

// Scratch as device globals (no runtime allocation allowed)
__device__ float g_gi[(size_t)RT * G3];   // 503 MB input-gate preactivations
__device__ float g_ys[(size_t)RT * HS];   // 168 MB layer outputs (reused per layer)

typedef unsigned long long ULL;

// packed f32x2 FMA (full fp32 rate on sm_103a requires fma.rn.f32x2)
__device__ __forceinline__ void fma2(ULL& d, ULL a, ULL b) {
    asm("fma.rn.f32x2 %0, %1, %2, %0;" : "+l"(d) : "l"(a), "l"(b));
}
__device__ __forceinline__ float2 unpk(ULL v) {
    float2 f; asm("mov.b64 {%0, %1}, %2;" : "=f"(f.x), "=f"(f.y) : "l"(v)); return f;
}
__device__ __forceinline__ float sigm(float x) { return 1.0f / (1.0f + __expf(-x)); }
__device__ __forceinline__ float tanh_(float x) { return 1.0f - 2.0f / (__expf(2.0f * x) + 1.0f); }

// ---------------------------------------------------------------------------
// gi GEMM:  gi[r,:] = xs[r,:] @ Wih^T + bih        (r = m*T + t)
// 256 threads, 64 rows/CTA. Warp = 8-row group; lane = quad-column of each gate.
// Thread tile: 8 rows x 2 col-pairs x 3 gates = 48 f32x2 accumulators.
// x tile stored DUPLICATED over k ([row][2k]) so one broadcast LDS.128 yields
// the (h,h) operands for TWO k's. Weights k-major, LDS.128 per gate per k.
// K=64 fuses the embedding (computes xe on the fly); K=128 reads g_ys.
// ---------------------------------------------------------------------------
template <int K>
__global__ __launch_bounds__(256) void gi_gemm(
    const float* __restrict__ Wih, const float* __restrict__ bih,
    const float* __restrict__ x,   const float* __restrict__ pea,
    const float* __restrict__ pet, const float* __restrict__ embW,
    const float* __restrict__ embB)
{
    extern __shared__ float sm[];
    float* Wt = sm;                 // [K][WTP]
    float* xT = sm + K * WTP;       // [64][XP]  dup over current 64-k chunk

    int tid = threadIdx.x;

    // transpose Wih (G3 x K) -> Wt[k][g]; lane==gate => conflict-free STS
    for (int g = tid; g < G3; g += 256) {
        const float* src = Wih + (size_t)g * K;
#pragma unroll 4
        for (int k0 = 0; k0 < K; k0 += 4) {
            float4 w = *(const float4*)(src + k0);
            Wt[(k0 + 0) * WTP + g] = w.x;
            Wt[(k0 + 1) * WTP + g] = w.y;
            Wt[(k0 + 2) * WTP + g] = w.z;
            Wt[(k0 + 3) * WTP + g] = w.w;
        }
    }

    int warp = tid >> 5;            // row-group 0..7
    int l    = tid & 31;            // quad-column 0..31
    int row0 = blockIdx.x * 64;

    ULL acc[3][8][2];
#pragma unroll
    for (int g = 0; g < 3; ++g)
#pragma unroll
        for (int j = 0; j < 8; ++j) { acc[g][j][0] = 0ULL; acc[g][j][1] = 0ULL; }

    constexpr int NCH = K / 64;
    for (int ch = 0; ch < NCH; ++ch) {
        __syncthreads();   // Wt ready / previous chunk's xT reads done
        // fill xT (duplicated): 64 rows x 16 float4
        for (int idx = tid; idx < 64 * 16; idx += 256) {
            int r = idx >> 4, kq = idx & 15;
            float4 v;
            if (K == 64) {
                // fused embedding: v_e = relu(emb_b + (x0+pe)W[e,0] + (x1+pe)W[e,1])
                int row = row0 + r;
                int t = row % Tt;
                int n = (row / Tt) & 7;
                float pe = __ldg(pet + t) + __ldg(pea + n);
                float2 xv = *(const float2*)(x + (size_t)row * 2);
                float x0 = xv.x + pe, x1 = xv.y + pe;
                float4 w0 = __ldg((const float4*)(embW + 8 * kq));
                float4 w1 = __ldg((const float4*)(embW + 8 * kq + 4));
                float4 b4 = __ldg((const float4*)(embB + 4 * kq));
                v.x = fmaxf(fmaf(x0, w0.x, fmaf(x1, w0.y, b4.x)), 0.0f);
                v.y = fmaxf(fmaf(x0, w0.z, fmaf(x1, w0.w, b4.y)), 0.0f);
                v.z = fmaxf(fmaf(x0, w1.x, fmaf(x1, w1.y, b4.z)), 0.0f);
                v.w = fmaxf(fmaf(x0, w1.z, fmaf(x1, w1.w, b4.w)), 0.0f);
            } else {
                v = *(const float4*)(g_ys + (size_t)(row0 + r) * K + ch * 64 + 4 * kq);
            }
            float* d = xT + r * XP + 8 * kq;
            *(float4*)(d)     = make_float4(v.x, v.x, v.y, v.y);
            *(float4*)(d + 4) = make_float4(v.z, v.z, v.w, v.w);
        }
        __syncthreads();

#pragma unroll 4
        for (int k2 = 0; k2 < 32; ++k2) {           // k-pairs within chunk
            int k = ch * 64 + 2 * k2;
            const float* wb = Wt + (size_t)k * WTP + 4 * l;
            ulonglong2 wA0 = *(const ulonglong2*)(wb);
            ulonglong2 wA1 = *(const ulonglong2*)(wb + 128);
            ulonglong2 wA2 = *(const ulonglong2*)(wb + 256);
            ulonglong2 wB0 = *(const ulonglong2*)(wb + WTP);
            ulonglong2 wB1 = *(const ulonglong2*)(wb + WTP + 128);
            ulonglong2 wB2 = *(const ulonglong2*)(wb + WTP + 256);
            const float* hb = xT + (warp * 8) * XP + 4 * k2;
#pragma unroll
            for (int j = 0; j < 8; ++j) {
                ulonglong2 h = *(const ulonglong2*)(hb + j * XP);  // (h_k dup, h_k1 dup)
                fma2(acc[0][j][0], h.x, wA0.x); fma2(acc[0][j][1], h.x, wA0.y);
                fma2(acc[1][j][0], h.x, wA1.x); fma2(acc[1][j][1], h.x, wA1.y);
                fma2(acc[2][j][0], h.x, wA2.x); fma2(acc[2][j][1], h.x, wA2.y);
                fma2(acc[0][j][0], h.y, wB0.x); fma2(acc[0][j][1], h.y, wB0.y);
                fma2(acc[1][j][0], h.y, wB1.x); fma2(acc[1][j][1], h.y, wB1.y);
                fma2(acc[2][j][0], h.y, wB2.x); fma2(acc[2][j][1], h.y, wB2.y);
            }
        }
    }

    // epilogue: bias + coalesced STG.128
#pragma unroll
    for (int g = 0; g < 3; ++g) {
        float4 b4 = __ldg((const float4*)(bih + g * 128 + 4 * l));
#pragma unroll
        for (int j = 0; j < 8; ++j) {
            float2 p0 = unpk(acc[g][j][0]);
            float2 p1 = unpk(acc[g][j][1]);
            float4 o = make_float4(p0.x + b4.x, p0.y + b4.y, p1.x + b4.z, p1.y + b4.w);
            *(float4*)(g_gi + (size_t)(row0 + warp * 8 + j) * G3 + g * 128 + 4 * l) = o;
        }
    }
}

// ---------------------------------------------------------------------------
// GRU recurrent scan for one layer.
// 1024 CTAs x 128 threads x 16 rows; all 20 steps on-chip (98.8% wave util).
// smem: Whh^T [128][WTP] fp32 + duplicated h tile [16 rows][HP] ([row][2k]).
// Thread tile: 8 rows x 1 col-pair x 3 gates. h update = 1 conflict-free
// STS.128 per row; h read = 1 broadcast LDS.128 per row per TWO k's.
// gi prefetched into registers before each step's k-loop.
// ---------------------------------------------------------------------------
__global__ __launch_bounds__(128) void scan_kernel(
    const float* __restrict__ Whh, const float* __restrict__ bhh,
    float* __restrict__ hid)
{
    extern __shared__ float sm[];
    float* Wt = sm;              // [128][WTP]
    float* hT = sm + HS * WTP;   // [16][HP]

    int tid = threadIdx.x;
    for (int g = tid; g < G3; g += 128) {
        const float* src = Whh + (size_t)g * HS;
#pragma unroll 4
        for (int k0 = 0; k0 < HS; k0 += 4) {
            float4 w = *(const float4*)(src + k0);
            Wt[(k0 + 0) * WTP + g] = w.x;
            Wt[(k0 + 1) * WTP + g] = w.y;
            Wt[(k0 + 2) * WTP + g] = w.z;
            Wt[(k0 + 3) * WTP + g] = w.w;
        }
    }
    for (int i = tid; i < 16 * HP; i += 128) hT[i] = 0.0f;   // h0 = 0

    int rg = tid >> 6;           // row-group 0..1 (8 rows each); uniform per warp
    int pp = tid & 63;           // column-pair 0..63
    int c2 = 2 * pp;
    int r0 = rg * 8;
    int m0 = blockIdx.x * 16;

    const float2 bR = *(const float2*)(bhh + c2);
    const float2 bZ = *(const float2*)(bhh + 128 + c2);
    const float2 bN = *(const float2*)(bhh + 256 + c2);

    float2 hreg[8];
#pragma unroll
    for (int j = 0; j < 8; ++j) hreg[j] = make_float2(0.0f, 0.0f);

    __syncthreads();

    for (int t = 0; t < Tt; ++t) {
        // prefetch gi for this step (independent of h -> hides DRAM latency)
        float2 giR[8], giZ[8], giN[8];
#pragma unroll
        for (int j = 0; j < 8; ++j) {
            const float* gp = g_gi + ((size_t)(m0 + r0 + j) * Tt + t) * G3;
            giR[j] = *(const float2*)(gp + c2);
            giZ[j] = *(const float2*)(gp + 128 + c2);
            giN[j] = *(const float2*)(gp + 256 + c2);
        }

        ULL aR[8], aZ[8], aN[8];
#pragma unroll
        for (int j = 0; j < 8; ++j) { aR[j] = 0ULL; aZ[j] = 0ULL; aN[j] = 0ULL; }

#pragma unroll 4
        for (int k2 = 0; k2 < 64; ++k2) {        // k-pairs
            const float* wb = Wt + (size_t)(2 * k2) * WTP + c2;
            ULL wr0 = *(const ULL*)(wb);
            ULL wz0 = *(const ULL*)(wb + 128);
            ULL wn0 = *(const ULL*)(wb + 256);
            ULL wr1 = *(const ULL*)(wb + WTP);
            ULL wz1 = *(const ULL*)(wb + WTP + 128);
            ULL wn1 = *(const ULL*)(wb + WTP + 256);
            const float* hb = hT + r0 * HP + 4 * k2;
#pragma unroll
            for (int j = 0; j < 8; ++j) {
                ulonglong2 h = *(const ulonglong2*)(hb + j * HP);  // (h_k dup, h_k1 dup)
                fma2(aR[j], h.x, wr0); fma2(aZ[j], h.x, wz0); fma2(aN[j], h.x, wn0);
                fma2(aR[j], h.y, wr1); fma2(aZ[j], h.y, wz1); fma2(aN[j], h.y, wn1);
            }
        }
        __syncthreads();   // all hT reads of this step done

#pragma unroll
        for (int j = 0; j < 8; ++j) {
            float2 ghR = unpk(aR[j]), ghZ = unpk(aZ[j]), ghN = unpk(aN[j]);
            float rv0 = sigm(giR[j].x + ghR.x + bR.x);
            float rv1 = sigm(giR[j].y + ghR.y + bR.y);
            float zv0 = sigm(giZ[j].x + ghZ.x + bZ.x);
            float zv1 = sigm(giZ[j].y + ghZ.y + bZ.y);
            float nv0 = tanh_(giN[j].x + rv0 * (ghN.x + bN.x));
            float nv1 = tanh_(giN[j].y + rv1 * (ghN.y + bN.y));
            float hn0 = (1.0f - zv0) * nv0 + zv0 * hreg[j].x;
            float hn1 = (1.0f - zv1) * nv1 + zv1 * hreg[j].y;
            hreg[j] = make_float2(hn0, hn1);
            *(float2*)(g_ys + ((size_t)(m0 + r0 + j) * Tt + t) * HS + c2) = hreg[j];
            // duplicated update: one conflict-free STS.128 (lanes stride 16B)
            *(float4*)(hT + (r0 + j) * HP + 4 * pp) = make_float4(hn0, hn0, hn1, hn1);
        }
        __syncthreads();   // new h visible before next k-loop
    }

    // hidden output: final h of rows with m % 8 == 7 -> j == 7 in each group
    int b = (m0 + r0 + 7) >> 3;
    *(float2*)(hid + (size_t)b * HS + c2) = hreg[7];
}

// ---------------------------------------------------------------------------
// Output projection  out[m, e] = ys_last[m, :] @ out_W[e, :] + out_b[e]
// ---------------------------------------------------------------------------
__global__ __launch_bounds__(256) void out_kernel(
    const float* __restrict__ oW, const float* __restrict__ ob,
    float* __restrict__ out)
{
    __shared__ float sW[128 * 64];   // transposed [k][e]
    int tid = threadIdx.x;
    for (int idx = tid; idx < 64 * 128; idx += 256) {
        int e = idx >> 7, k = idx & 127;
        sW[k * 64 + e] = oW[idx];
    }
    __syncthreads();
    int gid = blockIdx.x * 256 + tid;       // gid = m*64 + e
    int e = gid & 63;
    int m = gid >> 6;
    const float* ys = g_ys + ((size_t)m * Tt + (Tt - 1)) * HS;
    float acc = ob[e];
#pragma unroll 8
    for (int k = 0; k < 128; ++k) acc = fmaf(ys[k], sW[k * 64 + e], acc);
    out[gid] = acc;
}

// ---------------------------------------------------------------------------
// Launch
// ---------------------------------------------------------------------------
extern "C" void kernel_launch(void* const* d_in, const int* in_sizes, int n_in,
                              void* d_out, int out_size) {
    const float* x    = (const float*)d_in[0];
    const float* pea  = (const float*)d_in[1];
    const float* pet  = (const float*)d_in[2];
    const float* embW = (const float*)d_in[3];
    const float* embB = (const float*)d_in[4];
    const float* Wih0 = (const float*)d_in[5];
    const float* WihR = (const float*)d_in[6];   // (2, 384, 128)
    const float* Whh  = (const float*)d_in[7];   // (3, 384, 128)
    const float* bih  = (const float*)d_in[8];   // (3, 384)
    const float* bhh  = (const float*)d_in[9];   // (3, 384)
    const float* outW = (const float*)d_in[10];  // (64, 128)
    const float* outB = (const float*)d_in[11];

    float* out = (float*)d_out;                  // [Mm*64]
    float* hid = out + OUT0;                     // [3][Bb][HS]

    const int smem64   = 64  * WTP * 4 + 64 * XP * 4;   // 99328 + 32768 = 132096
    const int smem128  = 128 * WTP * 4 + 64 * XP * 4;   // 198656 + 32768 = 231424
    const int smemScan = 128 * WTP * 4 + 16 * HP * 4;   // 198656 + 16640 = 215296
    cudaFuncSetAttribute(gi_gemm<64>,  cudaFuncAttributeMaxDynamicSharedMemorySize, smem64);
    cudaFuncSetAttribute(gi_gemm<128>, cudaFuncAttributeMaxDynamicSharedMemorySize, smem128);
    cudaFuncSetAttribute(scan_kernel,  cudaFuncAttributeMaxDynamicSharedMemorySize, smemScan);

    // layer 0 (embedding fused into the gi x-tile fill)
    gi_gemm<64><<<RT / 64, 256, smem64>>>(Wih0, bih, x, pea, pet, embW, embB);
    scan_kernel<<<Mm / 16, 128, smemScan>>>(Whh, bhh, hid);
    // layer 1
    gi_gemm<128><<<RT / 64, 256, smem128>>>(WihR, bih + G3, x, pea, pet, embW, embB);
    scan_kernel<<<Mm / 16, 128, smemScan>>>(Whh + (size_t)G3 * HS, bhh + G3,
                                            hid + (size_t)Bb * HS);
    // layer 2
    gi_gemm<128><<<RT / 64, 256, smem128>>>(WihR + (size_t)G3 * HS, bih + 2 * G3,
                                            x, pea, pet, embW, embB);
    scan_kernel<<<Mm / 16, 128, smemScan>>>(Whh + (size_t)2 * G3 * HS, bhh + 2 * G3,
                                            hid + (size_t)2 * Bb * HS);

    out_kernel<<<(Mm * 64) / 256, 256>>>(outW, outB, out);
}

// round 7
// speedup vs baseline: 1.4067x; 1.4067x over previous
#include <cuda_runtime.h>

// ---------------------------------------------------------------------------
// Problem constants
// ---------------------------------------------------------------------------
constexpr int Bb  = 2048;
constexpr int Nn  = 8;
constexpr int Tt  = 20;
constexpr int Mm  = Bb * Nn;        // 16384 sequences
constexpr int ES  = 64;
constexpr int HS  = 128;
constexpr int G3  = 3 * HS;         // 384
constexpr int RT  = Mm * Tt;        // 327680 rows (m*T + t)
constexpr int WTP = 388;            // weight tile pitch (16B-aligned rows, conflict-free)
constexpr int XP  = 128;            // gi x-tile pitch (dup over 64-k chunk)
constexpr int HP  = 260;            // scan h-tile pitch (dup over 128 k)
constexpr int OUT0 = Mm * 64;       // first output section ("out")

// Scratch as device globals (no runtime allocation allowed)
__device__ float g_gi[(size_t)RT * G3];   // 503 MB input-gate preactivations
__device__ float g_ys[(size_t)RT * HS];   // 168 MB layer outputs (reused per layer)

typedef unsigned long long ULL;

// packed f32x2 FMA (full fp32 rate on sm_103a requires fma.rn.f32x2)
__device__ __forceinline__ void fma2(ULL& d, ULL a, ULL b) {
    asm("fma.rn.f32x2 %0, %1, %2, %0;" : "+l"(d) : "l"(a), "l"(b));
}
__device__ __forceinline__ float2 unpk(ULL v) {
    float2 f; asm("mov.b64 {%0, %1}, %2;" : "=f"(f.x), "=f"(f.y) : "l"(v)); return f;
}
__device__ __forceinline__ float sigm(float x) { return 1.0f / (1.0f + __expf(-x)); }
__device__ __forceinline__ float tanh_(float x) { return 1.0f - 2.0f / (__expf(2.0f * x) + 1.0f); }

// ---------------------------------------------------------------------------
// gi GEMM:  gi[r,:] = xs[r,:] @ Wih^T + bih        (r = m*T + t)
// 256 threads, 64 rows/CTA. Warp = 8-row group; lane = quad-column of each gate.
// Thread tile: 8 rows x 2 col-pairs x 3 gates = 48 f32x2 accumulators.
// x tile stored DUPLICATED over k ([row][2k]) so one broadcast LDS.128 yields
// the (h,h) operands for TWO k's. Weights k-major, LDS.128 per gate per k.
// K=64 fuses the embedding (computes xe on the fly); K=128 reads g_ys.
// ---------------------------------------------------------------------------
template <int K>
__global__ __launch_bounds__(256) void gi_gemm(
    const float* __restrict__ Wih, const float* __restrict__ bih,
    const float* __restrict__ x,   const float* __restrict__ pea,
    const float* __restrict__ pet, const float* __restrict__ embW,
    const float* __restrict__ embB)
{
    extern __shared__ float sm[];
    float* Wt = sm;                 // [K][WTP]
    float* xT = sm + K * WTP;       // [64][XP]  dup over current 64-k chunk

    int tid = threadIdx.x;

    // transpose Wih (G3 x K) -> Wt[k][g]; lane==gate => conflict-free STS
    for (int g = tid; g < G3; g += 256) {
        const float* src = Wih + (size_t)g * K;
#pragma unroll 4
        for (int k0 = 0; k0 < K; k0 += 4) {
            float4 w = *(const float4*)(src + k0);
            Wt[(k0 + 0) * WTP + g] = w.x;
            Wt[(k0 + 1) * WTP + g] = w.y;
            Wt[(k0 + 2) * WTP + g] = w.z;
            Wt[(k0 + 3) * WTP + g] = w.w;
        }
    }

    int warp = tid >> 5;            // row-group 0..7
    int l    = tid & 31;            // quad-column 0..31
    int row0 = blockIdx.x * 64;

    ULL acc[3][8][2];
#pragma unroll
    for (int g = 0; g < 3; ++g)
#pragma unroll
        for (int j = 0; j < 8; ++j) { acc[g][j][0] = 0ULL; acc[g][j][1] = 0ULL; }

    constexpr int NCH = K / 64;
    for (int ch = 0; ch < NCH; ++ch) {
        __syncthreads();   // Wt ready / previous chunk's xT reads done
        // fill xT (duplicated): 64 rows x 16 float4
        for (int idx = tid; idx < 64 * 16; idx += 256) {
            int r = idx >> 4, kq = idx & 15;
            float4 v;
            if (K == 64) {
                // fused embedding: v_e = relu(emb_b + (x0+pe)W[e,0] + (x1+pe)W[e,1])
                int row = row0 + r;
                int t = row % Tt;
                int n = (row / Tt) & 7;
                float pe = __ldg(pet + t) + __ldg(pea + n);
                float2 xv = *(const float2*)(x + (size_t)row * 2);
                float x0 = xv.x + pe, x1 = xv.y + pe;
                float4 w0 = __ldg((const float4*)(embW + 8 * kq));
                float4 w1 = __ldg((const float4*)(embW + 8 * kq + 4));
                float4 b4 = __ldg((const float4*)(embB + 4 * kq));
                v.x = fmaxf(fmaf(x0, w0.x, fmaf(x1, w0.y, b4.x)), 0.0f);
                v.y = fmaxf(fmaf(x0, w0.z, fmaf(x1, w0.w, b4.y)), 0.0f);
                v.z = fmaxf(fmaf(x0, w1.x, fmaf(x1, w1.y, b4.z)), 0.0f);
                v.w = fmaxf(fmaf(x0, w1.z, fmaf(x1, w1.w, b4.w)), 0.0f);
            } else {
                v = *(const float4*)(g_ys + (size_t)(row0 + r) * K + ch * 64 + 4 * kq);
            }
            float* d = xT + r * XP + 8 * kq;
            *(float4*)(d)     = make_float4(v.x, v.x, v.y, v.y);
            *(float4*)(d + 4) = make_float4(v.z, v.z, v.w, v.w);
        }
        __syncthreads();

#pragma unroll 4
        for (int k2 = 0; k2 < 32; ++k2) {           // k-pairs within chunk
            int k = ch * 64 + 2 * k2;
            const float* wb = Wt + (size_t)k * WTP + 4 * l;
            ulonglong2 wA0 = *(const ulonglong2*)(wb);
            ulonglong2 wA1 = *(const ulonglong2*)(wb + 128);
            ulonglong2 wA2 = *(const ulonglong2*)(wb + 256);
            ulonglong2 wB0 = *(const ulonglong2*)(wb + WTP);
            ulonglong2 wB1 = *(const ulonglong2*)(wb + WTP + 128);
            ulonglong2 wB2 = *(const ulonglong2*)(wb + WTP + 256);
            const float* hb = xT + (warp * 8) * XP + 4 * k2;
#pragma unroll
            for (int j = 0; j < 8; ++j) {
                ulonglong2 h = *(const ulonglong2*)(hb + j * XP);  // (h_k dup, h_k1 dup)
                fma2(acc[0][j][0], h.x, wA0.x); fma2(acc[0][j][1], h.x, wA0.y);
                fma2(acc[1][j][0], h.x, wA1.x); fma2(acc[1][j][1], h.x, wA1.y);
                fma2(acc[2][j][0], h.x, wA2.x); fma2(acc[2][j][1], h.x, wA2.y);
                fma2(acc[0][j][0], h.y, wB0.x); fma2(acc[0][j][1], h.y, wB0.y);
                fma2(acc[1][j][0], h.y, wB1.x); fma2(acc[1][j][1], h.y, wB1.y);
                fma2(acc[2][j][0], h.y, wB2.x); fma2(acc[2][j][1], h.y, wB2.y);
            }
        }
    }

    // epilogue: bias + coalesced STG.128
#pragma unroll
    for (int g = 0; g < 3; ++g) {
        float4 b4 = __ldg((const float4*)(bih + g * 128 + 4 * l));
#pragma unroll
        for (int j = 0; j < 8; ++j) {
            float2 p0 = unpk(acc[g][j][0]);
            float2 p1 = unpk(acc[g][j][1]);
            float4 o = make_float4(p0.x + b4.x, p0.y + b4.y, p1.x + b4.z, p1.y + b4.w);
            *(float4*)(g_gi + (size_t)(row0 + warp * 8 + j) * G3 + g * 128 + 4 * l) = o;
        }
    }
}

// ---------------------------------------------------------------------------
// GRU recurrent scan for one layer.
// 512 CTAs x 256 threads x 32 rows; all 20 steps on-chip.
// smem: Whh^T [128][WTP] fp32 + duplicated h tile [32 rows][HP] ([row][2k]).
// Thread tile: 8 rows x 1 col-pair x 3 gates (halves weight re-reads vs R5;
// 8 warps = 2/SMSP fixes R6's 1-warp/SMSP latency collapse).
// Per k-pair per warp: 6 weight LDS.64 (12 wf) + 8 broadcast LDS.128 h (8 wf)
// vs 48 fma2 -> LDS = 83% of the FMA floor => fma-bound.
// gi prefetched into registers before each step's k-loop.
// ---------------------------------------------------------------------------
__global__ __launch_bounds__(256) void scan_kernel(
    const float* __restrict__ Whh, const float* __restrict__ bhh,
    float* __restrict__ hid)
{
    extern __shared__ float sm[];
    float* Wt = sm;              // [128][WTP]
    float* hT = sm + HS * WTP;   // [32][HP]

    int tid = threadIdx.x;
    for (int g = tid; g < G3; g += 256) {
        const float* src = Whh + (size_t)g * HS;
#pragma unroll 4
        for (int k0 = 0; k0 < HS; k0 += 4) {
            float4 w = *(const float4*)(src + k0);
            Wt[(k0 + 0) * WTP + g] = w.x;
            Wt[(k0 + 1) * WTP + g] = w.y;
            Wt[(k0 + 2) * WTP + g] = w.z;
            Wt[(k0 + 3) * WTP + g] = w.w;
        }
    }
    for (int i = tid; i < 32 * HP; i += 256) hT[i] = 0.0f;   // h0 = 0

    int rg = tid >> 6;           // row-group 0..3 (8 rows each); uniform per warp
    int pp = tid & 63;           // column-pair 0..63
    int c2 = 2 * pp;
    int r0 = rg * 8;
    int m0 = blockIdx.x * 32;

    const float2 bR = *(const float2*)(bhh + c2);
    const float2 bZ = *(const float2*)(bhh + 128 + c2);
    const float2 bN = *(const float2*)(bhh + 256 + c2);

    float2 hreg[8];
#pragma unroll
    for (int j = 0; j < 8; ++j) hreg[j] = make_float2(0.0f, 0.0f);

    __syncthreads();

    for (int t = 0; t < Tt; ++t) {
        // prefetch gi for this step (independent of h -> overlaps the k-loop)
        float2 giR[8], giZ[8], giN[8];
#pragma unroll
        for (int j = 0; j < 8; ++j) {
            const float* gp = g_gi + ((size_t)(m0 + r0 + j) * Tt + t) * G3;
            giR[j] = *(const float2*)(gp + c2);
            giZ[j] = *(const float2*)(gp + 128 + c2);
            giN[j] = *(const float2*)(gp + 256 + c2);
        }

        ULL aR[8], aZ[8], aN[8];
#pragma unroll
        for (int j = 0; j < 8; ++j) { aR[j] = 0ULL; aZ[j] = 0ULL; aN[j] = 0ULL; }

#pragma unroll 4
        for (int k2 = 0; k2 < 64; ++k2) {        // k-pairs
            const float* wb = Wt + (size_t)(2 * k2) * WTP + c2;
            ULL wr0 = *(const ULL*)(wb);
            ULL wz0 = *(const ULL*)(wb + 128);
            ULL wn0 = *(const ULL*)(wb + 256);
            ULL wr1 = *(const ULL*)(wb + WTP);
            ULL wz1 = *(const ULL*)(wb + WTP + 128);
            ULL wn1 = *(const ULL*)(wb + WTP + 256);
            const float* hb = hT + r0 * HP + 4 * k2;
#pragma unroll
            for (int j = 0; j < 8; ++j) {
                ulonglong2 h = *(const ulonglong2*)(hb + j * HP);  // (h_k dup, h_k1 dup)
                fma2(aR[j], h.x, wr0); fma2(aZ[j], h.x, wz0); fma2(aN[j], h.x, wn0);
                fma2(aR[j], h.y, wr1); fma2(aZ[j], h.y, wz1); fma2(aN[j], h.y, wn1);
            }
        }
        __syncthreads();   // all hT reads of this step done

#pragma unroll
        for (int j = 0; j < 8; ++j) {
            float2 ghR = unpk(aR[j]), ghZ = unpk(aZ[j]), ghN = unpk(aN[j]);
            float rv0 = sigm(giR[j].x + ghR.x + bR.x);
            float rv1 = sigm(giR[j].y + ghR.y + bR.y);
            float zv0 = sigm(giZ[j].x + ghZ.x + bZ.x);
            float zv1 = sigm(giZ[j].y + ghZ.y + bZ.y);
            float nv0 = tanh_(giN[j].x + rv0 * (ghN.x + bN.x));
            float nv1 = tanh_(giN[j].y + rv1 * (ghN.y + bN.y));
            float hn0 = (1.0f - zv0) * nv0 + zv0 * hreg[j].x;
            float hn1 = (1.0f - zv1) * nv1 + zv1 * hreg[j].y;
            hreg[j] = make_float2(hn0, hn1);
            *(float2*)(g_ys + ((size_t)(m0 + r0 + j) * Tt + t) * HS + c2) = hreg[j];
            // duplicated update: one conflict-free STS.128 (lanes stride 16B)
            *(float4*)(hT + (r0 + j) * HP + 4 * pp) = make_float4(hn0, hn0, hn1, hn1);
        }
        __syncthreads();   // new h visible before next k-loop
    }

    // hidden output: final h of rows with m % 8 == 7 -> j == 7 in each group
    int b = (m0 + r0 + 7) >> 3;
    *(float2*)(hid + (size_t)b * HS + c2) = hreg[7];
}

// ---------------------------------------------------------------------------
// Output projection  out[m, e] = ys_last[m, :] @ out_W[e, :] + out_b[e]
// ---------------------------------------------------------------------------
__global__ __launch_bounds__(256) void out_kernel(
    const float* __restrict__ oW, const float* __restrict__ ob,
    float* __restrict__ out)
{
    __shared__ float sW[128 * 64];   // transposed [k][e]
    int tid = threadIdx.x;
    for (int idx = tid; idx < 64 * 128; idx += 256) {
        int e = idx >> 7, k = idx & 127;
        sW[k * 64 + e] = oW[idx];
    }
    __syncthreads();
    int gid = blockIdx.x * 256 + tid;       // gid = m*64 + e
    int e = gid & 63;
    int m = gid >> 6;
    const float* ys = g_ys + ((size_t)m * Tt + (Tt - 1)) * HS;
    float acc = ob[e];
#pragma unroll 8
    for (int k = 0; k < 128; ++k) acc = fmaf(ys[k], sW[k * 64 + e], acc);
    out[gid] = acc;
}

// ---------------------------------------------------------------------------
// Launch
// ---------------------------------------------------------------------------
extern "C" void kernel_launch(void* const* d_in, const int* in_sizes, int n_in,
                              void* d_out, int out_size) {
    const float* x    = (const float*)d_in[0];
    const float* pea  = (const float*)d_in[1];
    const float* pet  = (const float*)d_in[2];
    const float* embW = (const float*)d_in[3];
    const float* embB = (const float*)d_in[4];
    const float* Wih0 = (const float*)d_in[5];
    const float* WihR = (const float*)d_in[6];   // (2, 384, 128)
    const float* Whh  = (const float*)d_in[7];   // (3, 384, 128)
    const float* bih  = (const float*)d_in[8];   // (3, 384)
    const float* bhh  = (const float*)d_in[9];   // (3, 384)
    const float* outW = (const float*)d_in[10];  // (64, 128)
    const float* outB = (const float*)d_in[11];

    float* out = (float*)d_out;                  // [Mm*64]
    float* hid = out + OUT0;                     // [3][Bb][HS]

    const int smem64   = 64  * WTP * 4 + 64 * XP * 4;   // 99328 + 32768 = 132096
    const int smem128  = 128 * WTP * 4 + 64 * XP * 4;   // 198656 + 32768 = 231424
    const int smemScan = 128 * WTP * 4 + 32 * HP * 4;   // 198656 + 33280 = 231936
    cudaFuncSetAttribute(gi_gemm<64>,  cudaFuncAttributeMaxDynamicSharedMemorySize, smem64);
    cudaFuncSetAttribute(gi_gemm<128>, cudaFuncAttributeMaxDynamicSharedMemorySize, smem128);
    cudaFuncSetAttribute(scan_kernel,  cudaFuncAttributeMaxDynamicSharedMemorySize, smemScan);

    // layer 0 (embedding fused into the gi x-tile fill)
    gi_gemm<64><<<RT / 64, 256, smem64>>>(Wih0, bih, x, pea, pet, embW, embB);
    scan_kernel<<<Mm / 32, 256, smemScan>>>(Whh, bhh, hid);
    // layer 1
    gi_gemm<128><<<RT / 64, 256, smem128>>>(WihR, bih + G3, x, pea, pet, embW, embB);
    scan_kernel<<<Mm / 32, 256, smemScan>>>(Whh + (size_t)G3 * HS, bhh + G3,
                                            hid + (size_t)Bb * HS);
    // layer 2
    gi_gemm<128><<<RT / 64, 256, smem128>>>(WihR + (size_t)G3 * HS, bih + 2 * G3,
                                            x, pea, pet, embW, embB);
    scan_kernel<<<Mm / 32, 256, smemScan>>>(Whh + (size_t)2 * G3 * HS, bhh + 2 * G3,
                                            hid + (size_t)2 * Bb * HS);

    out_kernel<<<(Mm * 64) / 256, 256>>>(outW, outB, out);
}